// round 13
// baseline (speedup 1.0000x reference)
#include <cuda_runtime.h>
#include <cuda_bf16.h>
#include <cuda_fp16.h>
#include <cstdint>

// ---------------------------------------------------------------------------
// Fused LM-head + cross-entropy via legacy-path FP8 mma.sync, f16 accumulate.
// R11 structure (2431.7us: R7 core + SMSP de-phasing) with the de-phase
// offsets hoisted out of the mainloop (kills the ke-address ALU tax) and
// wider convert kernels (2x float4 per thread).
//   hidden [8192, 2048] fp32, weight [32000, 2048] fp32, targets [8192]
//   loss = mean_n ( log(sum_v exp(h_n . w_v)) - h_n . w_{t_n} )  (t != -100)
// W pre-scaled x32 before e4m3 quantization; epilogue multiplies by 1/32.
// tcgen05 unusable: harness PTX target is compute_103 (no 'a').
// DO NOT: pointer-increment loader (R8, -13%), full-kt frag batching (R9,
// spills at 128-reg cap, -12%).
// ---------------------------------------------------------------------------

#define N_TOK   8192
#define D_MODEL 2048
#define VOCAB   32000
#define IGNORE_IDX (-100)

#define BM 128
#define BN 256
#define BK 64
#define KITERS (D_MODEL / BK)    // 32
#define RS 80                    // padded smem row stride (bytes)
#define A_BYTES (BM * RS)        // 10240
#define B_BYTES (BN * RS)        // 20480
#define STAGE   (A_BYTES + B_BYTES)  // 30720
#define NSTAGE  3
#define SMEM_TOTAL (NSTAGE * STAGE)  // 92160; x2 CTAs = 184KB < 228KB

#define WSCALE 32.0f
#define INVS   (1.0f / 32.0f)

// Scratch (device globals referenced ONLY from device code)
__device__ uint8_t g_H8[(size_t)N_TOK * D_MODEL];
__device__ uint8_t g_W8[(size_t)VOCAB * D_MODEL];
__device__ float g_S[N_TOK];
__device__ float g_T[N_TOK];
__device__ int   g_tgt[N_TOK];

// ------------------------------ helpers ------------------------------------

__device__ __forceinline__ void cp_async16(uint32_t saddr, const void* gptr) {
    asm volatile("cp.async.cg.shared.global [%0], [%1], 16;\n" :: "r"(saddr), "l"(gptr));
}
__device__ __forceinline__ void cp_commit() { asm volatile("cp.async.commit_group;\n"); }
__device__ __forceinline__ void cp_wait0()  { asm volatile("cp.async.wait_group 0;\n"); }
__device__ __forceinline__ void cp_wait1()  { asm volatile("cp.async.wait_group 1;\n"); }

__device__ __forceinline__ uint16_t f2e4m3x2(float hi, float lo) {
    uint16_t r;
    asm("cvt.rn.satfinite.e4m3x2.f32 %0, %1, %2;" : "=h"(r) : "f"(hi), "f"(lo));
    return r;
}

__device__ __forceinline__ void ldsm_x4(uint32_t& r0, uint32_t& r1, uint32_t& r2, uint32_t& r3,
                                        uint32_t saddr) {
    asm volatile("ldmatrix.sync.aligned.m8n8.x4.shared.b16 {%0,%1,%2,%3}, [%4];"
                 : "=r"(r0), "=r"(r1), "=r"(r2), "=r"(r3) : "r"(saddr) : "memory");
}

// FP8 e4m3 mma with f16 accumulators
__device__ __forceinline__ void qmma_h(uint32_t c[2], const uint32_t a[4], const uint32_t b[2]) {
    asm("mma.sync.aligned.m16n8k32.row.col.f16.e4m3.e4m3.f16 "
        "{%0,%1}, {%2,%3,%4,%5}, {%6,%7}, {%0,%1};\n"
        : "+r"(c[0]), "+r"(c[1])
        : "r"(a[0]), "r"(a[1]), "r"(a[2]), "r"(a[3]),
          "r"(b[0]), "r"(b[1]));
}

// ------------------------------ small kernels -------------------------------

__global__ void setup_kernel(const int* __restrict__ traw) {
    __shared__ int s_is64;
    if (threadIdx.x == 0) {
        int is64 = 1;
        for (int j = 1; j < 128; j += 2) {
            int w = traw[j];
            if (w != 0 && w != -1) { is64 = 0; break; }
        }
        s_is64 = is64;
    }
    __syncthreads();
    const int is64 = s_is64;
    for (int i = threadIdx.x; i < N_TOK; i += blockDim.x) {
        g_tgt[i] = is64 ? traw[2 * i] : traw[i];
        g_S[i] = 0.0f;
        g_T[i] = 0.0f;
    }
}

// 2x float4 per thread for MLP=2 (DRAM-bound kernels)
__global__ void cvt_h_kernel(const float* __restrict__ src, int n4) {
    int i0 = (blockIdx.x * blockDim.x + threadIdx.x) * 2;
    #pragma unroll
    for (int j = 0; j < 2; j++) {
        int i = i0 + j;
        if (i < n4) {
            float4 v = reinterpret_cast<const float4*>(src)[i];
            uint32_t lo = f2e4m3x2(v.y, v.x);
            uint32_t hi = f2e4m3x2(v.w, v.z);
            reinterpret_cast<uint32_t*>(g_H8)[i] = (hi << 16) | lo;
        }
    }
}
__global__ void cvt_w_kernel(const float* __restrict__ src, int n4) {
    int i0 = (blockIdx.x * blockDim.x + threadIdx.x) * 2;
    #pragma unroll
    for (int j = 0; j < 2; j++) {
        int i = i0 + j;
        if (i < n4) {
            float4 v = reinterpret_cast<const float4*>(src)[i];
            uint32_t lo = f2e4m3x2(v.y * WSCALE, v.x * WSCALE);
            uint32_t hi = f2e4m3x2(v.w * WSCALE, v.z * WSCALE);
            reinterpret_cast<uint32_t*>(g_W8)[i] = (hi << 16) | lo;
        }
    }
}

// ------------------------------ GEMM + LSE ----------------------------------
// grid = (64 [x, fast], 125 [y]), 256 threads, 8 warps, warp tile 64x64.

__global__ __launch_bounds__(256, 2)
void gemm_lse_kernel() {
    extern __shared__ __align__(128) char smem[];
    const uint32_t smem_base = (uint32_t)__cvta_generic_to_shared(smem);
    const int tid = threadIdx.x, wid = tid >> 5, lane = tid & 31;
    const int wm = wid & 1, wn = wid >> 1;
    const int g = lane >> 2, tq = lane & 3;
    const int ksel = (wid >> 2) & 1;   // SMSP partners (wid, wid+4) get 0/1

    const int rowBlock = blockIdx.x * BM;
    const int colBlock = blockIdx.y * BN;
    const uint8_t* Ag = g_H8 + (size_t)rowBlock * D_MODEL;
    const uint8_t* Bg = g_W8 + (size_t)colBlock * D_MODEL;

    uint32_t acc[4][8][2];   // f16x2 pairs
    #pragma unroll
    for (int mi = 0; mi < 4; mi++)
        #pragma unroll
        for (int ni = 0; ni < 8; ni++) { acc[mi][ni][0] = 0u; acc[mi][ni][1] = 0u; }

    // ldmatrix lane-address components; de-phased k-half offsets HOISTED:
    // slot ks uses k-half (ks ^ ksel); addresses inside the loop are
    // SA + constant (same ALU profile as R7).
    const int lA_row = lane & 15;
    const int lA_off = (lane >> 4) * 16;
    const int lB_row = ((lane >> 4) & 1) * 8 + (lane & 7);
    const int lB_off = ((lane >> 3) & 1) * 16;
    const uint32_t aoff = (uint32_t)((wm * 64 + lA_row) * RS + lA_off);
    const uint32_t boff = (uint32_t)(A_BYTES + (wn * 64 + lB_row) * RS + lB_off);
    uint32_t aoff_k[2], boff_k[2];
    #pragma unroll
    for (int ks = 0; ks < 2; ks++) {
        const int ke = ks ^ ksel;
        aoff_k[ks] = aoff + ke * 32;
        boff_k[ks] = boff + ke * 32;
    }

    // stage loader (R7-proven form — keep as-is)
    auto load_stage = [&](int s, int kt) {
        const int k0 = kt * BK;
        const uint32_t base = smem_base + s * STAGE;
        #pragma unroll
        for (int j = 0; j < 2; j++) {
            int u = tid + j * 256;
            int r = u >> 2, c = u & 3;
            cp_async16(base + r * RS + c * 16,
                       Ag + (size_t)r * D_MODEL + k0 + c * 16);
        }
        #pragma unroll
        for (int j = 0; j < 4; j++) {
            int u = tid + j * 256;
            int r = u >> 2, c = u & 3;
            cp_async16(base + A_BYTES + r * RS + c * 16,
                       Bg + (size_t)r * D_MODEL + k0 + c * 16);
        }
        cp_commit();
    };

    load_stage(0, 0);
    load_stage(1, 1);

    for (int kt = 0; kt < KITERS; kt++) {
        if (kt + 1 < KITERS) cp_wait1(); else cp_wait0();
        __syncthreads();

        const uint32_t SA = smem_base + (kt % 3) * STAGE;

        #pragma unroll
        for (int ks = 0; ks < 2; ks++) {
            uint32_t bf[8][2], af[4][4];
            #pragma unroll
            for (int p = 0; p < 4; p++)
                ldsm_x4(bf[2*p][0], bf[2*p][1], bf[2*p+1][0], bf[2*p+1][1],
                        SA + boff_k[ks] + p * (16 * RS));
            #pragma unroll
            for (int mi = 0; mi < 4; mi++)
                ldsm_x4(af[mi][0], af[mi][1], af[mi][2], af[mi][3],
                        SA + aoff_k[ks] + mi * (16 * RS));
            #pragma unroll
            for (int mi = 0; mi < 4; mi++)
                #pragma unroll
                for (int ni = 0; ni < 8; ni++)
                    qmma_h(acc[mi][ni], af[mi], bf[ni]);
        }

        if (kt + 2 < KITERS) load_stage((kt + 2) % 3, kt + 2);
    }

    // Epilogue: acc[mi][ni][h] = f16x2 {col tq*2, tq*2+1} of row (g + h*8).
    #pragma unroll
    for (int mi = 0; mi < 4; mi++) {
        #pragma unroll
        for (int h = 0; h < 2; h++) {
            const int row = rowBlock + wm * 64 + mi * 16 + h * 8 + g;
            const int tgt = g_tgt[row];
            float s = 0.0f;
            #pragma unroll
            for (int ni = 0; ni < 8; ni++) {
                float2 vv = __half22float2(*reinterpret_cast<__half2*>(&acc[mi][ni][h]));
                float v0 = vv.x * INVS;
                float v1 = vv.y * INVS;
                const int tloc = tgt - colBlock - wn * 64 - ni * 8;
                if (tloc == tq * 2)     g_T[row] = v0;
                if (tloc == tq * 2 + 1) g_T[row] = v1;
                s += __expf(v0) + __expf(v1);
            }
            s += __shfl_xor_sync(0xffffffffu, s, 1);
            s += __shfl_xor_sync(0xffffffffu, s, 2);
            if (tq == 0) atomicAdd(&g_S[row], s);
        }
    }
}

__global__ void reduce_loss_kernel(float* __restrict__ out) {
    __shared__ float ssum[1024];
    __shared__ int   scnt[1024];
    int tid = threadIdx.x;
    float s = 0.0f;
    int cnt = 0;
    for (int i = tid; i < N_TOK; i += 1024) {
        int t = g_tgt[i];
        if (t != IGNORE_IDX) { s += logf(g_S[i]) - g_T[i]; cnt++; }
    }
    ssum[tid] = s; scnt[tid] = cnt;
    __syncthreads();
    for (int off = 512; off > 0; off >>= 1) {
        if (tid < off) { ssum[tid] += ssum[tid + off]; scnt[tid] += scnt[tid + off]; }
        __syncthreads();
    }
    if (tid == 0) out[0] = (scnt[0] > 0) ? ssum[0] / (float)scnt[0] : 0.0f;
}

// ------------------------------ launch --------------------------------------

extern "C" void kernel_launch(void* const* d_in, const int* in_sizes, int n_in,
                              void* d_out, int out_size) {
    const float* hidden = nullptr;
    const int*   traw   = nullptr;
    const float* weight = nullptr;
    for (int i = 0; i < n_in; i++) {
        long long sz = in_sizes[i];
        if (sz == (long long)N_TOK * D_MODEL)      hidden = (const float*)d_in[i];
        else if (sz == (long long)N_TOK)           traw   = (const int*)d_in[i];
        else if (sz == (long long)VOCAB * D_MODEL) weight = (const float*)d_in[i];
    }
    float* out = (float*)d_out;

    cudaFuncSetAttribute(gemm_lse_kernel,
                         cudaFuncAttributeMaxDynamicSharedMemorySize, SMEM_TOTAL);

    setup_kernel<<<1, 1024>>>(traw);

    {
        int n4 = (N_TOK * D_MODEL) / 4;
        cvt_h_kernel<<<(n4 / 2 + 255) / 256, 256>>>(hidden, n4);
    }
    {
        int n4 = (VOCAB * D_MODEL) / 4;
        cvt_w_kernel<<<(n4 / 2 + 255) / 256, 256>>>(weight, n4);
    }

    dim3 grid(N_TOK / BM, VOCAB / BN);   // x fast -> B-tile L2 reuse
    gemm_lse_kernel<<<grid, 256, SMEM_TOTAL>>>();

    reduce_loss_kernel<<<1, 1024>>>(out);
    (void)out_size;
}

// round 14
// speedup vs baseline: 1.0307x; 1.0307x over previous
#include <cuda_runtime.h>
#include <cuda_bf16.h>
#include <cuda_fp16.h>
#include <cstdint>

// ---------------------------------------------------------------------------
// Fused LM-head + cross-entropy via legacy-path FP8 mma.sync, f16 accumulate.
// GEMM mainloop is the R11 empirical optimum (2431.7us: R7 core + SMSP
// de-phasing with RUNTIME ke XOR — hoisting it regressed, R13). Converts are
// the widened MLP=2 versions (measured -5us, independent kernels).
//   hidden [8192, 2048] fp32, weight [32000, 2048] fp32, targets [8192]
//   loss = mean_n ( log(sum_v exp(h_n . w_v)) - h_n . w_{t_n} )  (t != -100)
// W pre-scaled x32 before e4m3 quantization; epilogue multiplies by 1/32.
// tcgen05 unusable: harness PTX target is compute_103 (no 'a').
// DO NOT TOUCH the mainloop: pointer-increment loader (R8, -13%), full-kt
// frag batching (R9, spills, -12%), ke-offset hoisting (R13, -3%).
// ---------------------------------------------------------------------------

#define N_TOK   8192
#define D_MODEL 2048
#define VOCAB   32000
#define IGNORE_IDX (-100)

#define BM 128
#define BN 256
#define BK 64
#define KITERS (D_MODEL / BK)    // 32
#define RS 80                    // padded smem row stride (bytes)
#define A_BYTES (BM * RS)        // 10240
#define B_BYTES (BN * RS)        // 20480
#define STAGE   (A_BYTES + B_BYTES)  // 30720
#define NSTAGE  3
#define SMEM_TOTAL (NSTAGE * STAGE)  // 92160; x2 CTAs = 184KB < 228KB

#define WSCALE 32.0f
#define INVS   (1.0f / 32.0f)

// Scratch (device globals referenced ONLY from device code)
__device__ uint8_t g_H8[(size_t)N_TOK * D_MODEL];
__device__ uint8_t g_W8[(size_t)VOCAB * D_MODEL];
__device__ float g_S[N_TOK];
__device__ float g_T[N_TOK];
__device__ int   g_tgt[N_TOK];

// ------------------------------ helpers ------------------------------------

__device__ __forceinline__ void cp_async16(uint32_t saddr, const void* gptr) {
    asm volatile("cp.async.cg.shared.global [%0], [%1], 16;\n" :: "r"(saddr), "l"(gptr));
}
__device__ __forceinline__ void cp_commit() { asm volatile("cp.async.commit_group;\n"); }
__device__ __forceinline__ void cp_wait0()  { asm volatile("cp.async.wait_group 0;\n"); }
__device__ __forceinline__ void cp_wait1()  { asm volatile("cp.async.wait_group 1;\n"); }

__device__ __forceinline__ uint16_t f2e4m3x2(float hi, float lo) {
    uint16_t r;
    asm("cvt.rn.satfinite.e4m3x2.f32 %0, %1, %2;" : "=h"(r) : "f"(hi), "f"(lo));
    return r;
}

__device__ __forceinline__ void ldsm_x4(uint32_t& r0, uint32_t& r1, uint32_t& r2, uint32_t& r3,
                                        uint32_t saddr) {
    asm volatile("ldmatrix.sync.aligned.m8n8.x4.shared.b16 {%0,%1,%2,%3}, [%4];"
                 : "=r"(r0), "=r"(r1), "=r"(r2), "=r"(r3) : "r"(saddr) : "memory");
}

// FP8 e4m3 mma with f16 accumulators
__device__ __forceinline__ void qmma_h(uint32_t c[2], const uint32_t a[4], const uint32_t b[2]) {
    asm("mma.sync.aligned.m16n8k32.row.col.f16.e4m3.e4m3.f16 "
        "{%0,%1}, {%2,%3,%4,%5}, {%6,%7}, {%0,%1};\n"
        : "+r"(c[0]), "+r"(c[1])
        : "r"(a[0]), "r"(a[1]), "r"(a[2]), "r"(a[3]),
          "r"(b[0]), "r"(b[1]));
}

// ------------------------------ small kernels -------------------------------

__global__ void setup_kernel(const int* __restrict__ traw) {
    __shared__ int s_is64;
    if (threadIdx.x == 0) {
        int is64 = 1;
        for (int j = 1; j < 128; j += 2) {
            int w = traw[j];
            if (w != 0 && w != -1) { is64 = 0; break; }
        }
        s_is64 = is64;
    }
    __syncthreads();
    const int is64 = s_is64;
    for (int i = threadIdx.x; i < N_TOK; i += blockDim.x) {
        g_tgt[i] = is64 ? traw[2 * i] : traw[i];
        g_S[i] = 0.0f;
        g_T[i] = 0.0f;
    }
}

// 2x float4 per thread for MLP=2 (DRAM-bound kernels; measured win R13)
__global__ void cvt_h_kernel(const float* __restrict__ src, int n4) {
    int i0 = (blockIdx.x * blockDim.x + threadIdx.x) * 2;
    #pragma unroll
    for (int j = 0; j < 2; j++) {
        int i = i0 + j;
        if (i < n4) {
            float4 v = reinterpret_cast<const float4*>(src)[i];
            uint32_t lo = f2e4m3x2(v.y, v.x);
            uint32_t hi = f2e4m3x2(v.w, v.z);
            reinterpret_cast<uint32_t*>(g_H8)[i] = (hi << 16) | lo;
        }
    }
}
__global__ void cvt_w_kernel(const float* __restrict__ src, int n4) {
    int i0 = (blockIdx.x * blockDim.x + threadIdx.x) * 2;
    #pragma unroll
    for (int j = 0; j < 2; j++) {
        int i = i0 + j;
        if (i < n4) {
            float4 v = reinterpret_cast<const float4*>(src)[i];
            uint32_t lo = f2e4m3x2(v.y * WSCALE, v.x * WSCALE);
            uint32_t hi = f2e4m3x2(v.w * WSCALE, v.z * WSCALE);
            reinterpret_cast<uint32_t*>(g_W8)[i] = (hi << 16) | lo;
        }
    }
}

// ------------------------------ GEMM + LSE ----------------------------------
// grid = (64 [x, fast], 125 [y]), 256 threads, 8 warps, warp tile 64x64.
// EXACT R11 mainloop (best measured GEMM: 2356us kernel time).

__global__ __launch_bounds__(256, 2)
void gemm_lse_kernel() {
    extern __shared__ __align__(128) char smem[];
    const uint32_t smem_base = (uint32_t)__cvta_generic_to_shared(smem);
    const int tid = threadIdx.x, wid = tid >> 5, lane = tid & 31;
    const int wm = wid & 1, wn = wid >> 1;
    const int g = lane >> 2, tq = lane & 3;
    const int ksel = (wid >> 2) & 1;   // SMSP partners (wid, wid+4) get 0/1

    const int rowBlock = blockIdx.x * BM;
    const int colBlock = blockIdx.y * BN;
    const uint8_t* Ag = g_H8 + (size_t)rowBlock * D_MODEL;
    const uint8_t* Bg = g_W8 + (size_t)colBlock * D_MODEL;

    uint32_t acc[4][8][2];   // f16x2 pairs
    #pragma unroll
    for (int mi = 0; mi < 4; mi++)
        #pragma unroll
        for (int ni = 0; ni < 8; ni++) { acc[mi][ni][0] = 0u; acc[mi][ni][1] = 0u; }

    // ldmatrix lane-address components
    const int lA_row = lane & 15;
    const int lA_off = (lane >> 4) * 16;
    const int lB_row = ((lane >> 4) & 1) * 8 + (lane & 7);
    const int lB_off = ((lane >> 3) & 1) * 16;
    const uint32_t aoff = (uint32_t)((wm * 64 + lA_row) * RS + lA_off);
    const uint32_t boff = (uint32_t)(A_BYTES + (wn * 64 + lB_row) * RS + lB_off);

    // stage loader (R7-proven form — keep as-is)
    auto load_stage = [&](int s, int kt) {
        const int k0 = kt * BK;
        const uint32_t base = smem_base + s * STAGE;
        #pragma unroll
        for (int j = 0; j < 2; j++) {
            int u = tid + j * 256;
            int r = u >> 2, c = u & 3;
            cp_async16(base + r * RS + c * 16,
                       Ag + (size_t)r * D_MODEL + k0 + c * 16);
        }
        #pragma unroll
        for (int j = 0; j < 4; j++) {
            int u = tid + j * 256;
            int r = u >> 2, c = u & 3;
            cp_async16(base + A_BYTES + r * RS + c * 16,
                       Bg + (size_t)r * D_MODEL + k0 + c * 16);
        }
        cp_commit();
    };

    load_stage(0, 0);
    load_stage(1, 1);

    for (int kt = 0; kt < KITERS; kt++) {
        if (kt + 1 < KITERS) cp_wait1(); else cp_wait0();
        __syncthreads();

        const uint32_t SA = smem_base + (kt % 3) * STAGE;

        #pragma unroll
        for (int ks = 0; ks < 2; ks++) {
            const int ke = ks ^ ksel;   // de-phase SMSP partner warps
            uint32_t bf[8][2], af[4][4];
            #pragma unroll
            for (int p = 0; p < 4; p++)
                ldsm_x4(bf[2*p][0], bf[2*p][1], bf[2*p+1][0], bf[2*p+1][1],
                        SA + boff + p * (16 * RS) + ke * 32);
            #pragma unroll
            for (int mi = 0; mi < 4; mi++)
                ldsm_x4(af[mi][0], af[mi][1], af[mi][2], af[mi][3],
                        SA + aoff + mi * (16 * RS) + ke * 32);
            #pragma unroll
            for (int mi = 0; mi < 4; mi++)
                #pragma unroll
                for (int ni = 0; ni < 8; ni++)
                    qmma_h(acc[mi][ni], af[mi], bf[ni]);
        }

        if (kt + 2 < KITERS) load_stage((kt + 2) % 3, kt + 2);
    }

    // Epilogue: acc[mi][ni][h] = f16x2 {col tq*2, tq*2+1} of row (g + h*8).
    #pragma unroll
    for (int mi = 0; mi < 4; mi++) {
        #pragma unroll
        for (int h = 0; h < 2; h++) {
            const int row = rowBlock + wm * 64 + mi * 16 + h * 8 + g;
            const int tgt = g_tgt[row];
            float s = 0.0f;
            #pragma unroll
            for (int ni = 0; ni < 8; ni++) {
                float2 vv = __half22float2(*reinterpret_cast<__half2*>(&acc[mi][ni][h]));
                float v0 = vv.x * INVS;
                float v1 = vv.y * INVS;
                const int tloc = tgt - colBlock - wn * 64 - ni * 8;
                if (tloc == tq * 2)     g_T[row] = v0;
                if (tloc == tq * 2 + 1) g_T[row] = v1;
                s += __expf(v0) + __expf(v1);
            }
            s += __shfl_xor_sync(0xffffffffu, s, 1);
            s += __shfl_xor_sync(0xffffffffu, s, 2);
            if (tq == 0) atomicAdd(&g_S[row], s);
        }
    }
}

__global__ void reduce_loss_kernel(float* __restrict__ out) {
    __shared__ float ssum[1024];
    __shared__ int   scnt[1024];
    int tid = threadIdx.x;
    float s = 0.0f;
    int cnt = 0;
    for (int i = tid; i < N_TOK; i += 1024) {
        int t = g_tgt[i];
        if (t != IGNORE_IDX) { s += logf(g_S[i]) - g_T[i]; cnt++; }
    }
    ssum[tid] = s; scnt[tid] = cnt;
    __syncthreads();
    for (int off = 512; off > 0; off >>= 1) {
        if (tid < off) { ssum[tid] += ssum[tid + off]; scnt[tid] += scnt[tid + off]; }
        __syncthreads();
    }
    if (tid == 0) out[0] = (scnt[0] > 0) ? ssum[0] / (float)scnt[0] : 0.0f;
}

// ------------------------------ launch --------------------------------------

extern "C" void kernel_launch(void* const* d_in, const int* in_sizes, int n_in,
                              void* d_out, int out_size) {
    const float* hidden = nullptr;
    const int*   traw   = nullptr;
    const float* weight = nullptr;
    for (int i = 0; i < n_in; i++) {
        long long sz = in_sizes[i];
        if (sz == (long long)N_TOK * D_MODEL)      hidden = (const float*)d_in[i];
        else if (sz == (long long)N_TOK)           traw   = (const int*)d_in[i];
        else if (sz == (long long)VOCAB * D_MODEL) weight = (const float*)d_in[i];
    }
    float* out = (float*)d_out;

    cudaFuncSetAttribute(gemm_lse_kernel,
                         cudaFuncAttributeMaxDynamicSharedMemorySize, SMEM_TOTAL);

    setup_kernel<<<1, 1024>>>(traw);

    {
        int n4 = (N_TOK * D_MODEL) / 4;
        cvt_h_kernel<<<(n4 / 2 + 255) / 256, 256>>>(hidden, n4);
    }
    {
        int n4 = (VOCAB * D_MODEL) / 4;
        cvt_w_kernel<<<(n4 / 2 + 255) / 256, 256>>>(weight, n4);
    }

    dim3 grid(N_TOK / BM, VOCAB / BN);   // x fast -> B-tile L2 reuse
    gemm_lse_kernel<<<grid, 256, SMEM_TOTAL>>>();

    reduce_loss_kernel<<<1, 1024>>>(out);
    (void)out_size;
}

// round 15
// speedup vs baseline: 1.0310x; 1.0003x over previous
#include <cuda_runtime.h>
#include <cuda_bf16.h>
#include <cuda_fp16.h>
#include <cstdint>

// ---------------------------------------------------------------------------
// Fused LM-head + cross-entropy via legacy-path FP8 mma.sync, f16 accumulate.
// GEMM mainloop is the R11/R14 empirical optimum (2357us kernel time, tensor
// 75.0%) — BYTE-IDENTICAL here. This round only optimizes the small kernels:
// MLP=4 converts, multi-block setup.
//   hidden [8192, 2048] fp32, weight [32000, 2048] fp32, targets [8192]
//   loss = mean_n ( log(sum_v exp(h_n . w_v)) - h_n . w_{t_n} )  (t != -100)
// W pre-scaled x32 before e4m3 quantization; epilogue multiplies by 1/32.
// tcgen05 unusable: harness PTX target is compute_103 (no 'a').
// DO NOT TOUCH the mainloop: pointer-increment loader (R8, -13%), full-kt
// frag batching (R9, spills, -12%), ke-offset hoisting (R13, -3%).
// ---------------------------------------------------------------------------

#define N_TOK   8192
#define D_MODEL 2048
#define VOCAB   32000
#define IGNORE_IDX (-100)

#define BM 128
#define BN 256
#define BK 64
#define KITERS (D_MODEL / BK)    // 32
#define RS 80                    // padded smem row stride (bytes)
#define A_BYTES (BM * RS)        // 10240
#define B_BYTES (BN * RS)        // 20480
#define STAGE   (A_BYTES + B_BYTES)  // 30720
#define NSTAGE  3
#define SMEM_TOTAL (NSTAGE * STAGE)  // 92160; x2 CTAs = 184KB < 228KB

#define WSCALE 32.0f
#define INVS   (1.0f / 32.0f)

// Scratch (device globals referenced ONLY from device code)
__device__ uint8_t g_H8[(size_t)N_TOK * D_MODEL];
__device__ uint8_t g_W8[(size_t)VOCAB * D_MODEL];
__device__ float g_S[N_TOK];
__device__ float g_T[N_TOK];
__device__ int   g_tgt[N_TOK];

// ------------------------------ helpers ------------------------------------

__device__ __forceinline__ void cp_async16(uint32_t saddr, const void* gptr) {
    asm volatile("cp.async.cg.shared.global [%0], [%1], 16;\n" :: "r"(saddr), "l"(gptr));
}
__device__ __forceinline__ void cp_commit() { asm volatile("cp.async.commit_group;\n"); }
__device__ __forceinline__ void cp_wait0()  { asm volatile("cp.async.wait_group 0;\n"); }
__device__ __forceinline__ void cp_wait1()  { asm volatile("cp.async.wait_group 1;\n"); }

__device__ __forceinline__ uint16_t f2e4m3x2(float hi, float lo) {
    uint16_t r;
    asm("cvt.rn.satfinite.e4m3x2.f32 %0, %1, %2;" : "=h"(r) : "f"(hi), "f"(lo));
    return r;
}

__device__ __forceinline__ void ldsm_x4(uint32_t& r0, uint32_t& r1, uint32_t& r2, uint32_t& r3,
                                        uint32_t saddr) {
    asm volatile("ldmatrix.sync.aligned.m8n8.x4.shared.b16 {%0,%1,%2,%3}, [%4];"
                 : "=r"(r0), "=r"(r1), "=r"(r2), "=r"(r3) : "r"(saddr) : "memory");
}

// FP8 e4m3 mma with f16 accumulators
__device__ __forceinline__ void qmma_h(uint32_t c[2], const uint32_t a[4], const uint32_t b[2]) {
    asm("mma.sync.aligned.m16n8k32.row.col.f16.e4m3.e4m3.f16 "
        "{%0,%1}, {%2,%3,%4,%5}, {%6,%7}, {%0,%1};\n"
        : "+r"(c[0]), "+r"(c[1])
        : "r"(a[0]), "r"(a[1]), "r"(a[2]), "r"(a[3]),
          "r"(b[0]), "r"(b[1]));
}

// ------------------------------ small kernels -------------------------------

// Multi-block setup: every block independently derives the is64 flag from the
// same 128 header words (L2 broadcast), then grid-strides the init.
__global__ void setup_kernel(const int* __restrict__ traw) {
    __shared__ int s_is64;
    if (threadIdx.x == 0) {
        int is64 = 1;
        for (int j = 1; j < 128; j += 2) {
            int w = traw[j];
            if (w != 0 && w != -1) { is64 = 0; break; }
        }
        s_is64 = is64;
    }
    __syncthreads();
    const int is64 = s_is64;
    const int stride = gridDim.x * blockDim.x;
    for (int i = blockIdx.x * blockDim.x + threadIdx.x; i < N_TOK; i += stride) {
        g_tgt[i] = is64 ? traw[2 * i] : traw[i];
        g_S[i] = 0.0f;
        g_T[i] = 0.0f;
    }
}

// 4x float4 per thread for MLP=4 (DRAM-bound; PTW/latency fully overlapped)
__global__ void cvt_h_kernel(const float* __restrict__ src, int n4) {
    int i0 = (blockIdx.x * blockDim.x + threadIdx.x) * 4;
    #pragma unroll
    for (int j = 0; j < 4; j++) {
        int i = i0 + j;
        if (i < n4) {
            float4 v = reinterpret_cast<const float4*>(src)[i];
            uint32_t lo = f2e4m3x2(v.y, v.x);
            uint32_t hi = f2e4m3x2(v.w, v.z);
            reinterpret_cast<uint32_t*>(g_H8)[i] = (hi << 16) | lo;
        }
    }
}
__global__ void cvt_w_kernel(const float* __restrict__ src, int n4) {
    int i0 = (blockIdx.x * blockDim.x + threadIdx.x) * 4;
    #pragma unroll
    for (int j = 0; j < 4; j++) {
        int i = i0 + j;
        if (i < n4) {
            float4 v = reinterpret_cast<const float4*>(src)[i];
            uint32_t lo = f2e4m3x2(v.y * WSCALE, v.x * WSCALE);
            uint32_t hi = f2e4m3x2(v.w * WSCALE, v.z * WSCALE);
            reinterpret_cast<uint32_t*>(g_W8)[i] = (hi << 16) | lo;
        }
    }
}

// ------------------------------ GEMM + LSE ----------------------------------
// grid = (64 [x, fast], 125 [y]), 256 threads, 8 warps, warp tile 64x64.
// EXACT R11/R14 mainloop (best measured: 2357us kernel time, tensor 75.0%).

__global__ __launch_bounds__(256, 2)
void gemm_lse_kernel() {
    extern __shared__ __align__(128) char smem[];
    const uint32_t smem_base = (uint32_t)__cvta_generic_to_shared(smem);
    const int tid = threadIdx.x, wid = tid >> 5, lane = tid & 31;
    const int wm = wid & 1, wn = wid >> 1;
    const int g = lane >> 2, tq = lane & 3;
    const int ksel = (wid >> 2) & 1;   // SMSP partners (wid, wid+4) get 0/1

    const int rowBlock = blockIdx.x * BM;
    const int colBlock = blockIdx.y * BN;
    const uint8_t* Ag = g_H8 + (size_t)rowBlock * D_MODEL;
    const uint8_t* Bg = g_W8 + (size_t)colBlock * D_MODEL;

    uint32_t acc[4][8][2];   // f16x2 pairs
    #pragma unroll
    for (int mi = 0; mi < 4; mi++)
        #pragma unroll
        for (int ni = 0; ni < 8; ni++) { acc[mi][ni][0] = 0u; acc[mi][ni][1] = 0u; }

    // ldmatrix lane-address components
    const int lA_row = lane & 15;
    const int lA_off = (lane >> 4) * 16;
    const int lB_row = ((lane >> 4) & 1) * 8 + (lane & 7);
    const int lB_off = ((lane >> 3) & 1) * 16;
    const uint32_t aoff = (uint32_t)((wm * 64 + lA_row) * RS + lA_off);
    const uint32_t boff = (uint32_t)(A_BYTES + (wn * 64 + lB_row) * RS + lB_off);

    // stage loader (R7-proven form — keep as-is)
    auto load_stage = [&](int s, int kt) {
        const int k0 = kt * BK;
        const uint32_t base = smem_base + s * STAGE;
        #pragma unroll
        for (int j = 0; j < 2; j++) {
            int u = tid + j * 256;
            int r = u >> 2, c = u & 3;
            cp_async16(base + r * RS + c * 16,
                       Ag + (size_t)r * D_MODEL + k0 + c * 16);
        }
        #pragma unroll
        for (int j = 0; j < 4; j++) {
            int u = tid + j * 256;
            int r = u >> 2, c = u & 3;
            cp_async16(base + A_BYTES + r * RS + c * 16,
                       Bg + (size_t)r * D_MODEL + k0 + c * 16);
        }
        cp_commit();
    };

    load_stage(0, 0);
    load_stage(1, 1);

    for (int kt = 0; kt < KITERS; kt++) {
        if (kt + 1 < KITERS) cp_wait1(); else cp_wait0();
        __syncthreads();

        const uint32_t SA = smem_base + (kt % 3) * STAGE;

        #pragma unroll
        for (int ks = 0; ks < 2; ks++) {
            const int ke = ks ^ ksel;   // de-phase SMSP partner warps
            uint32_t bf[8][2], af[4][4];
            #pragma unroll
            for (int p = 0; p < 4; p++)
                ldsm_x4(bf[2*p][0], bf[2*p][1], bf[2*p+1][0], bf[2*p+1][1],
                        SA + boff + p * (16 * RS) + ke * 32);
            #pragma unroll
            for (int mi = 0; mi < 4; mi++)
                ldsm_x4(af[mi][0], af[mi][1], af[mi][2], af[mi][3],
                        SA + aoff + mi * (16 * RS) + ke * 32);
            #pragma unroll
            for (int mi = 0; mi < 4; mi++)
                #pragma unroll
                for (int ni = 0; ni < 8; ni++)
                    qmma_h(acc[mi][ni], af[mi], bf[ni]);
        }

        if (kt + 2 < KITERS) load_stage((kt + 2) % 3, kt + 2);
    }

    // Epilogue: acc[mi][ni][h] = f16x2 {col tq*2, tq*2+1} of row (g + h*8).
    #pragma unroll
    for (int mi = 0; mi < 4; mi++) {
        #pragma unroll
        for (int h = 0; h < 2; h++) {
            const int row = rowBlock + wm * 64 + mi * 16 + h * 8 + g;
            const int tgt = g_tgt[row];
            float s = 0.0f;
            #pragma unroll
            for (int ni = 0; ni < 8; ni++) {
                float2 vv = __half22float2(*reinterpret_cast<__half2*>(&acc[mi][ni][h]));
                float v0 = vv.x * INVS;
                float v1 = vv.y * INVS;
                const int tloc = tgt - colBlock - wn * 64 - ni * 8;
                if (tloc == tq * 2)     g_T[row] = v0;
                if (tloc == tq * 2 + 1) g_T[row] = v1;
                s += __expf(v0) + __expf(v1);
            }
            s += __shfl_xor_sync(0xffffffffu, s, 1);
            s += __shfl_xor_sync(0xffffffffu, s, 2);
            if (tq == 0) atomicAdd(&g_S[row], s);
        }
    }
}

__global__ void reduce_loss_kernel(float* __restrict__ out) {
    __shared__ float ssum[1024];
    __shared__ int   scnt[1024];
    int tid = threadIdx.x;
    float s = 0.0f;
    int cnt = 0;
    for (int i = tid; i < N_TOK; i += 1024) {
        int t = g_tgt[i];
        if (t != IGNORE_IDX) { s += logf(g_S[i]) - g_T[i]; cnt++; }
    }
    ssum[tid] = s; scnt[tid] = cnt;
    __syncthreads();
    for (int off = 512; off > 0; off >>= 1) {
        if (tid < off) { ssum[tid] += ssum[tid + off]; scnt[tid] += scnt[tid + off]; }
        __syncthreads();
    }
    if (tid == 0) out[0] = (scnt[0] > 0) ? ssum[0] / (float)scnt[0] : 0.0f;
}

// ------------------------------ launch --------------------------------------

extern "C" void kernel_launch(void* const* d_in, const int* in_sizes, int n_in,
                              void* d_out, int out_size) {
    const float* hidden = nullptr;
    const int*   traw   = nullptr;
    const float* weight = nullptr;
    for (int i = 0; i < n_in; i++) {
        long long sz = in_sizes[i];
        if (sz == (long long)N_TOK * D_MODEL)      hidden = (const float*)d_in[i];
        else if (sz == (long long)N_TOK)           traw   = (const int*)d_in[i];
        else if (sz == (long long)VOCAB * D_MODEL) weight = (const float*)d_in[i];
    }
    float* out = (float*)d_out;

    cudaFuncSetAttribute(gemm_lse_kernel,
                         cudaFuncAttributeMaxDynamicSharedMemorySize, SMEM_TOTAL);

    setup_kernel<<<32, 256>>>(traw);

    {
        int n4 = (N_TOK * D_MODEL) / 4;
        cvt_h_kernel<<<(n4 / 4 + 255) / 256, 256>>>(hidden, n4);
    }
    {
        int n4 = (VOCAB * D_MODEL) / 4;
        cvt_w_kernel<<<(n4 / 4 + 255) / 256, 256>>>(weight, n4);
    }

    dim3 grid(N_TOK / BM, VOCAB / BN);   // x fast -> B-tile L2 reuse
    gemm_lse_kernel<<<grid, 256, SMEM_TOTAL>>>();

    reduce_loss_kernel<<<1, 1024>>>(out);
    (void)out_size;
}

// round 16
// speedup vs baseline: 1.0912x; 1.0583x over previous
#include <cuda_runtime.h>
#include <cuda_bf16.h>
#include <cuda_fp16.h>
#include <cstdint>

// ---------------------------------------------------------------------------
// Fused LM-head + cross-entropy via legacy-path FP8 mma.sync, f16 accumulate.
// R15 consume/loader bodies BYTE-IDENTICAL; block-wide __syncthreads stage
// handoff replaced by mbarrier full/empty pairs so warps decouple instead of
// convoying (targets the 25% tensor idle at occ=24.7%).
//   hidden [8192, 2048] fp32, weight [32000, 2048] fp32, targets [8192]
//   loss = mean_n ( log(sum_v exp(h_n . w_v)) - h_n . w_{t_n} )  (t != -100)
// W pre-scaled x32 before e4m3 quantization; epilogue multiplies by 1/32.
// tcgen05 unusable: harness PTX target is compute_103 (no 'a'); mbarrier /
// cp.async.mbarrier.arrive are baseline sm_80/90 features and compile.
// DO NOT TOUCH the inner loop: pointer-increment loader (R8, -13%), full-kt
// frag batching (R9, spills, -12%), ke-offset hoisting (R13, -3%).
// ---------------------------------------------------------------------------

#define N_TOK   8192
#define D_MODEL 2048
#define VOCAB   32000
#define IGNORE_IDX (-100)

#define BM 128
#define BN 256
#define BK 64
#define KITERS (D_MODEL / BK)    // 32
#define RS 80                    // padded smem row stride (bytes)
#define A_BYTES (BM * RS)        // 10240
#define B_BYTES (BN * RS)        // 20480
#define STAGE   (A_BYTES + B_BYTES)  // 30720
#define NSTAGE  3
#define MBAR_OFF (NSTAGE * STAGE)        // barriers after stages
#define SMEM_TOTAL (MBAR_OFF + 64)       // 92224; x2 CTAs = 184448 < 228KB

#define WSCALE 32.0f
#define INVS   (1.0f / 32.0f)

// Scratch (device globals referenced ONLY from device code)
__device__ uint8_t g_H8[(size_t)N_TOK * D_MODEL];
__device__ uint8_t g_W8[(size_t)VOCAB * D_MODEL];
__device__ float g_S[N_TOK];
__device__ float g_T[N_TOK];
__device__ int   g_tgt[N_TOK];

// ------------------------------ helpers ------------------------------------

__device__ __forceinline__ void cp_async16(uint32_t saddr, const void* gptr) {
    asm volatile("cp.async.cg.shared.global [%0], [%1], 16;\n" :: "r"(saddr), "l"(gptr));
}

__device__ __forceinline__ void mbar_init(uint32_t a, uint32_t cnt) {
    asm volatile("mbarrier.init.shared.b64 [%0], %1;" :: "r"(a), "r"(cnt) : "memory");
}
__device__ __forceinline__ void mbar_arrive(uint32_t a) {
    asm volatile("mbarrier.arrive.shared.b64 _, [%0];" :: "r"(a) : "memory");
}
// arrive fires when all of this thread's prior cp.asyncs have completed
__device__ __forceinline__ void cpasync_mbar_arrive(uint32_t a) {
    asm volatile("cp.async.mbarrier.arrive.noinc.shared.b64 [%0];" :: "r"(a) : "memory");
}
__device__ __forceinline__ void mbar_wait(uint32_t a, uint32_t parity) {
    asm volatile(
        "{\n\t.reg .pred P;\n"
        "W%=:\n\t"
        "mbarrier.try_wait.parity.acquire.cta.shared::cta.b64 P, [%0], %1;\n\t"
        "@!P bra W%=;\n\t}"
        :: "r"(a), "r"(parity) : "memory");
}

__device__ __forceinline__ uint16_t f2e4m3x2(float hi, float lo) {
    uint16_t r;
    asm("cvt.rn.satfinite.e4m3x2.f32 %0, %1, %2;" : "=h"(r) : "f"(hi), "f"(lo));
    return r;
}

__device__ __forceinline__ void ldsm_x4(uint32_t& r0, uint32_t& r1, uint32_t& r2, uint32_t& r3,
                                        uint32_t saddr) {
    asm volatile("ldmatrix.sync.aligned.m8n8.x4.shared.b16 {%0,%1,%2,%3}, [%4];"
                 : "=r"(r0), "=r"(r1), "=r"(r2), "=r"(r3) : "r"(saddr) : "memory");
}

// FP8 e4m3 mma with f16 accumulators
__device__ __forceinline__ void qmma_h(uint32_t c[2], const uint32_t a[4], const uint32_t b[2]) {
    asm("mma.sync.aligned.m16n8k32.row.col.f16.e4m3.e4m3.f16 "
        "{%0,%1}, {%2,%3,%4,%5}, {%6,%7}, {%0,%1};\n"
        : "+r"(c[0]), "+r"(c[1])
        : "r"(a[0]), "r"(a[1]), "r"(a[2]), "r"(a[3]),
          "r"(b[0]), "r"(b[1]));
}

// ------------------------------ small kernels -------------------------------

__global__ void setup_kernel(const int* __restrict__ traw) {
    __shared__ int s_is64;
    if (threadIdx.x == 0) {
        int is64 = 1;
        for (int j = 1; j < 128; j += 2) {
            int w = traw[j];
            if (w != 0 && w != -1) { is64 = 0; break; }
        }
        s_is64 = is64;
    }
    __syncthreads();
    const int is64 = s_is64;
    const int stride = gridDim.x * blockDim.x;
    for (int i = blockIdx.x * blockDim.x + threadIdx.x; i < N_TOK; i += stride) {
        g_tgt[i] = is64 ? traw[2 * i] : traw[i];
        g_S[i] = 0.0f;
        g_T[i] = 0.0f;
    }
}

__global__ void cvt_h_kernel(const float* __restrict__ src, int n4) {
    int i0 = (blockIdx.x * blockDim.x + threadIdx.x) * 4;
    #pragma unroll
    for (int j = 0; j < 4; j++) {
        int i = i0 + j;
        if (i < n4) {
            float4 v = reinterpret_cast<const float4*>(src)[i];
            uint32_t lo = f2e4m3x2(v.y, v.x);
            uint32_t hi = f2e4m3x2(v.w, v.z);
            reinterpret_cast<uint32_t*>(g_H8)[i] = (hi << 16) | lo;
        }
    }
}
__global__ void cvt_w_kernel(const float* __restrict__ src, int n4) {
    int i0 = (blockIdx.x * blockDim.x + threadIdx.x) * 4;
    #pragma unroll
    for (int j = 0; j < 4; j++) {
        int i = i0 + j;
        if (i < n4) {
            float4 v = reinterpret_cast<const float4*>(src)[i];
            uint32_t lo = f2e4m3x2(v.y * WSCALE, v.x * WSCALE);
            uint32_t hi = f2e4m3x2(v.w * WSCALE, v.z * WSCALE);
            reinterpret_cast<uint32_t*>(g_W8)[i] = (hi << 16) | lo;
        }
    }
}

// ------------------------------ GEMM + LSE ----------------------------------
// grid = (64 [x, fast], 125 [y]), 256 threads, 8 warps, warp tile 64x64.

__global__ __launch_bounds__(256, 2)
void gemm_lse_kernel() {
    extern __shared__ __align__(128) char smem[];
    const uint32_t smem_base = (uint32_t)__cvta_generic_to_shared(smem);
    const int tid = threadIdx.x, wid = tid >> 5, lane = tid & 31;
    const int wm = wid & 1, wn = wid >> 1;
    const int g = lane >> 2, tq = lane & 3;
    const int ksel = (wid >> 2) & 1;   // SMSP partners (wid, wid+4) get 0/1

    const int rowBlock = blockIdx.x * BM;
    const int colBlock = blockIdx.y * BN;
    const uint8_t* Ag = g_H8 + (size_t)rowBlock * D_MODEL;
    const uint8_t* Bg = g_W8 + (size_t)colBlock * D_MODEL;

    // mbarrier block: full[0..2] at +0,8,16 ; empty[0..2] at +24,32,40
    const uint32_t FULLB = smem_base + MBAR_OFF;
    const uint32_t EMPTB = FULLB + 24;
    if (tid == 0) {
        #pragma unroll
        for (int s = 0; s < NSTAGE; s++) {
            mbar_init(FULLB + s * 8, 256);
            mbar_init(EMPTB + s * 8, 256);
        }
    }
    __syncthreads();

    uint32_t acc[4][8][2];   // f16x2 pairs
    #pragma unroll
    for (int mi = 0; mi < 4; mi++)
        #pragma unroll
        for (int ni = 0; ni < 8; ni++) { acc[mi][ni][0] = 0u; acc[mi][ni][1] = 0u; }

    // ldmatrix lane-address components
    const int lA_row = lane & 15;
    const int lA_off = (lane >> 4) * 16;
    const int lB_row = ((lane >> 4) & 1) * 8 + (lane & 7);
    const int lB_off = ((lane >> 3) & 1) * 16;
    const uint32_t aoff = (uint32_t)((wm * 64 + lA_row) * RS + lA_off);
    const uint32_t boff = (uint32_t)(A_BYTES + (wn * 64 + lB_row) * RS + lB_off);

    // stage loader (R7-proven body) + cp.async-completion arrive on full[s]
    auto load_stage = [&](int s, int kt) {
        const int k0 = kt * BK;
        const uint32_t base = smem_base + s * STAGE;
        #pragma unroll
        for (int j = 0; j < 2; j++) {
            int u = tid + j * 256;
            int r = u >> 2, c = u & 3;
            cp_async16(base + r * RS + c * 16,
                       Ag + (size_t)r * D_MODEL + k0 + c * 16);
        }
        #pragma unroll
        for (int j = 0; j < 4; j++) {
            int u = tid + j * 256;
            int r = u >> 2, c = u & 3;
            cp_async16(base + A_BYTES + r * RS + c * 16,
                       Bg + (size_t)r * D_MODEL + k0 + c * 16);
        }
        cpasync_mbar_arrive(FULLB + s * 8);
    };

    load_stage(0, 0);
    load_stage(1, 1);

    int s = 0, n3 = 0;   // s = kt%3, n3 = kt/3 (use index of stage s)
    for (int kt = 0; kt < KITERS; kt++) {
        mbar_wait(FULLB + s * 8, (uint32_t)(n3 & 1));

        const uint32_t SA = smem_base + s * STAGE;

        #pragma unroll
        for (int ks = 0; ks < 2; ks++) {
            const int ke = ks ^ ksel;   // de-phase SMSP partner warps
            uint32_t bf[8][2], af[4][4];
            #pragma unroll
            for (int p = 0; p < 4; p++)
                ldsm_x4(bf[2*p][0], bf[2*p][1], bf[2*p+1][0], bf[2*p+1][1],
                        SA + boff + p * (16 * RS) + ke * 32);
            #pragma unroll
            for (int mi = 0; mi < 4; mi++)
                ldsm_x4(af[mi][0], af[mi][1], af[mi][2], af[mi][3],
                        SA + aoff + mi * (16 * RS) + ke * 32);
            #pragma unroll
            for (int mi = 0; mi < 4; mi++)
                #pragma unroll
                for (int ni = 0; ni < 8; ni++)
                    qmma_h(acc[mi][ni], af[mi], bf[ni]);
        }

        mbar_arrive(EMPTB + s * 8);    // this warp done reading stage s

        if (kt + 2 < KITERS) {
            int s2 = s + 2; if (s2 >= NSTAGE) s2 -= NSTAGE;
            if (kt >= 1) {
                // stage s2 last consumed at kt-1; its use index there was
                // (kt-1)/3 = n3 - (s==0 ? 1 : 0)
                uint32_t ep = (uint32_t)((s == 0 ? (n3 ^ 1) : n3) & 1);
                mbar_wait(EMPTB + s2 * 8, ep);
            }
            load_stage(s2, kt + 2);
        }

        s++; if (s == NSTAGE) { s = 0; n3++; }
    }

    // Epilogue: acc[mi][ni][h] = f16x2 {col tq*2, tq*2+1} of row (g + h*8).
    #pragma unroll
    for (int mi = 0; mi < 4; mi++) {
        #pragma unroll
        for (int h = 0; h < 2; h++) {
            const int row = rowBlock + wm * 64 + mi * 16 + h * 8 + g;
            const int tgt = g_tgt[row];
            float sx = 0.0f;
            #pragma unroll
            for (int ni = 0; ni < 8; ni++) {
                float2 vv = __half22float2(*reinterpret_cast<__half2*>(&acc[mi][ni][h]));
                float v0 = vv.x * INVS;
                float v1 = vv.y * INVS;
                const int tloc = tgt - colBlock - wn * 64 - ni * 8;
                if (tloc == tq * 2)     g_T[row] = v0;
                if (tloc == tq * 2 + 1) g_T[row] = v1;
                sx += __expf(v0) + __expf(v1);
            }
            sx += __shfl_xor_sync(0xffffffffu, sx, 1);
            sx += __shfl_xor_sync(0xffffffffu, sx, 2);
            if (tq == 0) atomicAdd(&g_S[row], sx);
        }
    }
}

__global__ void reduce_loss_kernel(float* __restrict__ out) {
    __shared__ float ssum[1024];
    __shared__ int   scnt[1024];
    int tid = threadIdx.x;
    float s = 0.0f;
    int cnt = 0;
    for (int i = tid; i < N_TOK; i += 1024) {
        int t = g_tgt[i];
        if (t != IGNORE_IDX) { s += logf(g_S[i]) - g_T[i]; cnt++; }
    }
    ssum[tid] = s; scnt[tid] = cnt;
    __syncthreads();
    for (int off = 512; off > 0; off >>= 1) {
        if (tid < off) { ssum[tid] += ssum[tid + off]; scnt[tid] += scnt[tid + off]; }
        __syncthreads();
    }
    if (tid == 0) out[0] = (scnt[0] > 0) ? ssum[0] / (float)scnt[0] : 0.0f;
}

// ------------------------------ launch --------------------------------------

extern "C" void kernel_launch(void* const* d_in, const int* in_sizes, int n_in,
                              void* d_out, int out_size) {
    const float* hidden = nullptr;
    const int*   traw   = nullptr;
    const float* weight = nullptr;
    for (int i = 0; i < n_in; i++) {
        long long sz = in_sizes[i];
        if (sz == (long long)N_TOK * D_MODEL)      hidden = (const float*)d_in[i];
        else if (sz == (long long)N_TOK)           traw   = (const int*)d_in[i];
        else if (sz == (long long)VOCAB * D_MODEL) weight = (const float*)d_in[i];
    }
    float* out = (float*)d_out;

    cudaFuncSetAttribute(gemm_lse_kernel,
                         cudaFuncAttributeMaxDynamicSharedMemorySize, SMEM_TOTAL);

    setup_kernel<<<32, 256>>>(traw);

    {
        int n4 = (N_TOK * D_MODEL) / 4;
        cvt_h_kernel<<<(n4 / 4 + 255) / 256, 256>>>(hidden, n4);
    }
    {
        int n4 = (VOCAB * D_MODEL) / 4;
        cvt_w_kernel<<<(n4 / 4 + 255) / 256, 256>>>(weight, n4);
    }

    dim3 grid(N_TOK / BM, VOCAB / BN);   // x fast -> B-tile L2 reuse
    gemm_lse_kernel<<<grid, 256, SMEM_TOTAL>>>();

    reduce_loss_kernel<<<1, 1024>>>(out);
    (void)out_size;
}

// round 17
// speedup vs baseline: 1.0935x; 1.0021x over previous
#include <cuda_runtime.h>
#include <cuda_bf16.h>
#include <cuda_fp16.h>
#include <cstdint>

// ---------------------------------------------------------------------------
// Fused LM-head + cross-entropy via legacy-path FP8 mma.sync, f16 accumulate.
// R16 (2289.9us: mbarrier producer/consumer staging, tensor 79.4%) with ONE
// change: the empty[s] arrive moves up to right after the last LDSM of the
// stage (reads done; trailing QMMAs are register-only), shrinking the
// stage-recycle critical path that producers spin on.
//   hidden [8192, 2048] fp32, weight [32000, 2048] fp32, targets [8192]
//   loss = mean_n ( log(sum_v exp(h_n . w_v)) - h_n . w_{t_n} )  (t != -100)
// W pre-scaled x32 before e4m3 quantization; epilogue multiplies by 1/32.
// tcgen05 unusable: harness PTX target is compute_103 (no 'a').
// DO NOT TOUCH the inner loop bodies: pointer-increment loader (R8, -13%),
// full-kt frag batching (R9, spills, -12%), ke-offset hoisting (R13, -3%).
// ---------------------------------------------------------------------------

#define N_TOK   8192
#define D_MODEL 2048
#define VOCAB   32000
#define IGNORE_IDX (-100)

#define BM 128
#define BN 256
#define BK 64
#define KITERS (D_MODEL / BK)    // 32
#define RS 80                    // padded smem row stride (bytes)
#define A_BYTES (BM * RS)        // 10240
#define B_BYTES (BN * RS)        // 20480
#define STAGE   (A_BYTES + B_BYTES)  // 30720
#define NSTAGE  3
#define MBAR_OFF (NSTAGE * STAGE)        // barriers after stages
#define SMEM_TOTAL (MBAR_OFF + 64)       // 92224; x2 CTAs = 184448 < 228KB

#define WSCALE 32.0f
#define INVS   (1.0f / 32.0f)

// Scratch (device globals referenced ONLY from device code)
__device__ uint8_t g_H8[(size_t)N_TOK * D_MODEL];
__device__ uint8_t g_W8[(size_t)VOCAB * D_MODEL];
__device__ float g_S[N_TOK];
__device__ float g_T[N_TOK];
__device__ int   g_tgt[N_TOK];

// ------------------------------ helpers ------------------------------------

__device__ __forceinline__ void cp_async16(uint32_t saddr, const void* gptr) {
    asm volatile("cp.async.cg.shared.global [%0], [%1], 16;\n" :: "r"(saddr), "l"(gptr));
}

__device__ __forceinline__ void mbar_init(uint32_t a, uint32_t cnt) {
    asm volatile("mbarrier.init.shared.b64 [%0], %1;" :: "r"(a), "r"(cnt) : "memory");
}
__device__ __forceinline__ void mbar_arrive(uint32_t a) {
    asm volatile("mbarrier.arrive.shared.b64 _, [%0];" :: "r"(a) : "memory");
}
// arrive fires when all of this thread's prior cp.asyncs have completed
__device__ __forceinline__ void cpasync_mbar_arrive(uint32_t a) {
    asm volatile("cp.async.mbarrier.arrive.noinc.shared.b64 [%0];" :: "r"(a) : "memory");
}
__device__ __forceinline__ void mbar_wait(uint32_t a, uint32_t parity) {
    asm volatile(
        "{\n\t.reg .pred P;\n"
        "W%=:\n\t"
        "mbarrier.try_wait.parity.acquire.cta.shared::cta.b64 P, [%0], %1;\n\t"
        "@!P bra W%=;\n\t}"
        :: "r"(a), "r"(parity) : "memory");
}

__device__ __forceinline__ uint16_t f2e4m3x2(float hi, float lo) {
    uint16_t r;
    asm("cvt.rn.satfinite.e4m3x2.f32 %0, %1, %2;" : "=h"(r) : "f"(hi), "f"(lo));
    return r;
}

__device__ __forceinline__ void ldsm_x4(uint32_t& r0, uint32_t& r1, uint32_t& r2, uint32_t& r3,
                                        uint32_t saddr) {
    asm volatile("ldmatrix.sync.aligned.m8n8.x4.shared.b16 {%0,%1,%2,%3}, [%4];"
                 : "=r"(r0), "=r"(r1), "=r"(r2), "=r"(r3) : "r"(saddr) : "memory");
}

// FP8 e4m3 mma with f16 accumulators
__device__ __forceinline__ void qmma_h(uint32_t c[2], const uint32_t a[4], const uint32_t b[2]) {
    asm("mma.sync.aligned.m16n8k32.row.col.f16.e4m3.e4m3.f16 "
        "{%0,%1}, {%2,%3,%4,%5}, {%6,%7}, {%0,%1};\n"
        : "+r"(c[0]), "+r"(c[1])
        : "r"(a[0]), "r"(a[1]), "r"(a[2]), "r"(a[3]),
          "r"(b[0]), "r"(b[1]));
}

// ------------------------------ small kernels -------------------------------

__global__ void setup_kernel(const int* __restrict__ traw) {
    __shared__ int s_is64;
    if (threadIdx.x == 0) {
        int is64 = 1;
        for (int j = 1; j < 128; j += 2) {
            int w = traw[j];
            if (w != 0 && w != -1) { is64 = 0; break; }
        }
        s_is64 = is64;
    }
    __syncthreads();
    const int is64 = s_is64;
    const int stride = gridDim.x * blockDim.x;
    for (int i = blockIdx.x * blockDim.x + threadIdx.x; i < N_TOK; i += stride) {
        g_tgt[i] = is64 ? traw[2 * i] : traw[i];
        g_S[i] = 0.0f;
        g_T[i] = 0.0f;
    }
}

__global__ void cvt_h_kernel(const float* __restrict__ src, int n4) {
    int i0 = (blockIdx.x * blockDim.x + threadIdx.x) * 4;
    #pragma unroll
    for (int j = 0; j < 4; j++) {
        int i = i0 + j;
        if (i < n4) {
            float4 v = reinterpret_cast<const float4*>(src)[i];
            uint32_t lo = f2e4m3x2(v.y, v.x);
            uint32_t hi = f2e4m3x2(v.w, v.z);
            reinterpret_cast<uint32_t*>(g_H8)[i] = (hi << 16) | lo;
        }
    }
}
__global__ void cvt_w_kernel(const float* __restrict__ src, int n4) {
    int i0 = (blockIdx.x * blockDim.x + threadIdx.x) * 4;
    #pragma unroll
    for (int j = 0; j < 4; j++) {
        int i = i0 + j;
        if (i < n4) {
            float4 v = reinterpret_cast<const float4*>(src)[i];
            uint32_t lo = f2e4m3x2(v.y * WSCALE, v.x * WSCALE);
            uint32_t hi = f2e4m3x2(v.w * WSCALE, v.z * WSCALE);
            reinterpret_cast<uint32_t*>(g_W8)[i] = (hi << 16) | lo;
        }
    }
}

// ------------------------------ GEMM + LSE ----------------------------------
// grid = (64 [x, fast], 125 [y]), 256 threads, 8 warps, warp tile 64x64.

__global__ __launch_bounds__(256, 2)
void gemm_lse_kernel() {
    extern __shared__ __align__(128) char smem[];
    const uint32_t smem_base = (uint32_t)__cvta_generic_to_shared(smem);
    const int tid = threadIdx.x, wid = tid >> 5, lane = tid & 31;
    const int wm = wid & 1, wn = wid >> 1;
    const int g = lane >> 2, tq = lane & 3;
    const int ksel = (wid >> 2) & 1;   // SMSP partners (wid, wid+4) get 0/1

    const int rowBlock = blockIdx.x * BM;
    const int colBlock = blockIdx.y * BN;
    const uint8_t* Ag = g_H8 + (size_t)rowBlock * D_MODEL;
    const uint8_t* Bg = g_W8 + (size_t)colBlock * D_MODEL;

    // mbarrier block: full[0..2] at +0,8,16 ; empty[0..2] at +24,32,40
    const uint32_t FULLB = smem_base + MBAR_OFF;
    const uint32_t EMPTB = FULLB + 24;
    if (tid == 0) {
        #pragma unroll
        for (int s = 0; s < NSTAGE; s++) {
            mbar_init(FULLB + s * 8, 256);
            mbar_init(EMPTB + s * 8, 256);
        }
    }
    __syncthreads();

    uint32_t acc[4][8][2];   // f16x2 pairs
    #pragma unroll
    for (int mi = 0; mi < 4; mi++)
        #pragma unroll
        for (int ni = 0; ni < 8; ni++) { acc[mi][ni][0] = 0u; acc[mi][ni][1] = 0u; }

    // ldmatrix lane-address components
    const int lA_row = lane & 15;
    const int lA_off = (lane >> 4) * 16;
    const int lB_row = ((lane >> 4) & 1) * 8 + (lane & 7);
    const int lB_off = ((lane >> 3) & 1) * 16;
    const uint32_t aoff = (uint32_t)((wm * 64 + lA_row) * RS + lA_off);
    const uint32_t boff = (uint32_t)(A_BYTES + (wn * 64 + lB_row) * RS + lB_off);

    // stage loader (R7-proven body) + cp.async-completion arrive on full[s]
    auto load_stage = [&](int s, int kt) {
        const int k0 = kt * BK;
        const uint32_t base = smem_base + s * STAGE;
        #pragma unroll
        for (int j = 0; j < 2; j++) {
            int u = tid + j * 256;
            int r = u >> 2, c = u & 3;
            cp_async16(base + r * RS + c * 16,
                       Ag + (size_t)r * D_MODEL + k0 + c * 16);
        }
        #pragma unroll
        for (int j = 0; j < 4; j++) {
            int u = tid + j * 256;
            int r = u >> 2, c = u & 3;
            cp_async16(base + A_BYTES + r * RS + c * 16,
                       Bg + (size_t)r * D_MODEL + k0 + c * 16);
        }
        cpasync_mbar_arrive(FULLB + s * 8);
    };

    load_stage(0, 0);
    load_stage(1, 1);

    int s = 0, n3 = 0;   // s = kt%3, n3 = kt/3 (use index of stage s)
    for (int kt = 0; kt < KITERS; kt++) {
        mbar_wait(FULLB + s * 8, (uint32_t)(n3 & 1));

        const uint32_t SA = smem_base + s * STAGE;

        #pragma unroll
        for (int ks = 0; ks < 2; ks++) {
            const int ke = ks ^ ksel;   // de-phase SMSP partner warps
            uint32_t bf[8][2], af[4][4];
            #pragma unroll
            for (int p = 0; p < 4; p++)
                ldsm_x4(bf[2*p][0], bf[2*p][1], bf[2*p+1][0], bf[2*p+1][1],
                        SA + boff + p * (16 * RS) + ke * 32);
            #pragma unroll
            for (int mi = 0; mi < 4; mi++)
                ldsm_x4(af[mi][0], af[mi][1], af[mi][2], af[mi][3],
                        SA + aoff + mi * (16 * RS) + ke * 32);
            // After the LAST LDSM of this stage, the warp no longer reads
            // smem stage s — signal empty early (arrive has release
            // semantics, ordered after the LDSM reads). Trailing QMMAs are
            // register-only.
            if (ks == 1) mbar_arrive(EMPTB + s * 8);
            #pragma unroll
            for (int mi = 0; mi < 4; mi++)
                #pragma unroll
                for (int ni = 0; ni < 8; ni++)
                    qmma_h(acc[mi][ni], af[mi], bf[ni]);
        }

        if (kt + 2 < KITERS) {
            int s2 = s + 2; if (s2 >= NSTAGE) s2 -= NSTAGE;
            if (kt >= 1) {
                // stage s2 last consumed at kt-1; its use index there was
                // (kt-1)/3 = n3 - (s==0 ? 1 : 0)
                uint32_t ep = (uint32_t)((s == 0 ? (n3 ^ 1) : n3) & 1);
                mbar_wait(EMPTB + s2 * 8, ep);
            }
            load_stage(s2, kt + 2);
        }

        s++; if (s == NSTAGE) { s = 0; n3++; }
    }

    // Epilogue: acc[mi][ni][h] = f16x2 {col tq*2, tq*2+1} of row (g + h*8).
    #pragma unroll
    for (int mi = 0; mi < 4; mi++) {
        #pragma unroll
        for (int h = 0; h < 2; h++) {
            const int row = rowBlock + wm * 64 + mi * 16 + h * 8 + g;
            const int tgt = g_tgt[row];
            float sx = 0.0f;
            #pragma unroll
            for (int ni = 0; ni < 8; ni++) {
                float2 vv = __half22float2(*reinterpret_cast<__half2*>(&acc[mi][ni][h]));
                float v0 = vv.x * INVS;
                float v1 = vv.y * INVS;
                const int tloc = tgt - colBlock - wn * 64 - ni * 8;
                if (tloc == tq * 2)     g_T[row] = v0;
                if (tloc == tq * 2 + 1) g_T[row] = v1;
                sx += __expf(v0) + __expf(v1);
            }
            sx += __shfl_xor_sync(0xffffffffu, sx, 1);
            sx += __shfl_xor_sync(0xffffffffu, sx, 2);
            if (tq == 0) atomicAdd(&g_S[row], sx);
        }
    }
}

__global__ void reduce_loss_kernel(float* __restrict__ out) {
    __shared__ float ssum[1024];
    __shared__ int   scnt[1024];
    int tid = threadIdx.x;
    float s = 0.0f;
    int cnt = 0;
    for (int i = tid; i < N_TOK; i += 1024) {
        int t = g_tgt[i];
        if (t != IGNORE_IDX) { s += logf(g_S[i]) - g_T[i]; cnt++; }
    }
    ssum[tid] = s; scnt[tid] = cnt;
    __syncthreads();
    for (int off = 512; off > 0; off >>= 1) {
        if (tid < off) { ssum[tid] += ssum[tid + off]; scnt[tid] += scnt[tid + off]; }
        __syncthreads();
    }
    if (tid == 0) out[0] = (scnt[0] > 0) ? ssum[0] / (float)scnt[0] : 0.0f;
}

// ------------------------------ launch --------------------------------------

extern "C" void kernel_launch(void* const* d_in, const int* in_sizes, int n_in,
                              void* d_out, int out_size) {
    const float* hidden = nullptr;
    const int*   traw   = nullptr;
    const float* weight = nullptr;
    for (int i = 0; i < n_in; i++) {
        long long sz = in_sizes[i];
        if (sz == (long long)N_TOK * D_MODEL)      hidden = (const float*)d_in[i];
        else if (sz == (long long)N_TOK)           traw   = (const int*)d_in[i];
        else if (sz == (long long)VOCAB * D_MODEL) weight = (const float*)d_in[i];
    }
    float* out = (float*)d_out;

    cudaFuncSetAttribute(gemm_lse_kernel,
                         cudaFuncAttributeMaxDynamicSharedMemorySize, SMEM_TOTAL);

    setup_kernel<<<32, 256>>>(traw);

    {
        int n4 = (N_TOK * D_MODEL) / 4;
        cvt_h_kernel<<<(n4 / 4 + 255) / 256, 256>>>(hidden, n4);
    }
    {
        int n4 = (VOCAB * D_MODEL) / 4;
        cvt_w_kernel<<<(n4 / 4 + 255) / 256, 256>>>(weight, n4);
    }

    dim3 grid(N_TOK / BM, VOCAB / BN);   // x fast -> B-tile L2 reuse
    gemm_lse_kernel<<<grid, 256, SMEM_TOTAL>>>();

    reduce_loss_kernel<<<1, 1024>>>(out);
    (void)out_size;
}